// round 7
// baseline (speedup 1.0000x reference)
#include <cuda_runtime.h>
#include <cstdint>
#include <math.h>

#define T_STEPS 512
#define BATCH   32
#define EMBED   512
#define HID     1024
#define G4      4096

#define NB  128
#define NT  512
#define WSS 1028            // padded W row stride (banks 4*rg distinct, 16B aligned)
#define PRS 33              // partials row stride
#define PKS (32 * PRS)      // partials per k-slice

#define OFF_HN ((size_t)BATCH * T_STEPS * HID)
#define OFF_CN (OFF_HN + (size_t)BATCH * HID)

typedef unsigned long long u64;

__device__ float g_xproj[(size_t)T_STEPS * G4 * BATCH]; // [t][j][b]
__device__ float g_h[2][BATCH * HID];
__device__ unsigned g_count;
__device__ volatile unsigned g_gen;

__device__ __forceinline__ void ffma2(u64 &d, u64 a, u64 b) {
    asm("fma.rn.f32x2 %0, %1, %2, %0;" : "+l"(d) : "l"(a), "l"(b));
}
__device__ __forceinline__ u64 pk2(float x, float y) {
    u64 r; asm("mov.b64 %0, {%1, %2};" : "=l"(r) : "f"(x), "f"(y)); return r;
}
__device__ __forceinline__ float2 upk(u64 v) {
    float2 r; asm("mov.b64 {%0, %1}, %2;" : "=f"(r.x), "=f"(r.y) : "l"(v)); return r;
}

__device__ __forceinline__ void grid_barrier() {
    __syncthreads();
    if (threadIdx.x == 0) {
        unsigned gen = g_gen;
        __threadfence();
        unsigned prev = atomicAdd(&g_count, 1u);
        if (prev == NB - 1) {
            g_count = 0;
            __threadfence();
            g_gen = gen + 1;
        } else {
            while (g_gen == gen) { __nanosleep(32); }
        }
        __threadfence();
    }
    __syncthreads();
}

// ---------------------------------------------------------------------------
// Kernel 1: x_proj[t][j][b] = sum_e emb[ids[b][t]][e] * Wih[j][e]
// 128x128x8 SGEMM, packed f32x2 accumulators. (unchanged)
// ---------------------------------------------------------------------------
__global__ void __launch_bounds__(256, 2) xproj_gemm(
    const int* __restrict__ ids,
    const float* __restrict__ emb,
    const float* __restrict__ Wih)
{
    __shared__ float As[8][132];
    __shared__ float Bs[8][132];

    const int m0  = blockIdx.y * 128;
    const int n0  = blockIdx.x * 128;
    const int tid = threadIdx.x;

    const int mm = tid >> 1;
    const int qa = tid & 1;
    const int gm = m0 + mm;
    const int tt = gm >> 5;
    const int bb = gm & 31;
    const float* arow = emb + (size_t)ids[bb * T_STEPS + tt] * EMBED;
    const float* brow = Wih + (size_t)(n0 + mm) * EMBED;

    const int tm = tid >> 4;
    const int tn = tid & 15;

    u64 accp[8][4];
#pragma unroll
    for (int i = 0; i < 8; i++)
#pragma unroll
        for (int j = 0; j < 4; j++) accp[i][j] = 0ull;

    for (int k0 = 0; k0 < EMBED; k0 += 8) {
        float4 av = *(const float4*)(arow + k0 + qa * 4);
        float4 bv = *(const float4*)(brow + k0 + qa * 4);
        __syncthreads();
        As[qa * 4 + 0][mm] = av.x; As[qa * 4 + 1][mm] = av.y;
        As[qa * 4 + 2][mm] = av.z; As[qa * 4 + 3][mm] = av.w;
        Bs[qa * 4 + 0][mm] = bv.x; Bs[qa * 4 + 1][mm] = bv.y;
        Bs[qa * 4 + 2][mm] = bv.z; Bs[qa * 4 + 3][mm] = bv.w;
        __syncthreads();

#pragma unroll
        for (int kk = 0; kk < 8; kk++) {
            float4 a0 = *(const float4*)(&As[kk][tm * 8]);
            float4 a1 = *(const float4*)(&As[kk][tm * 8 + 4]);
            const u64* bp = (const u64*)(&Bs[kk][tn * 8]);
            u64 b0 = bp[0], b1 = bp[1], b2 = bp[2], b3 = bp[3];
            u64 ad[8];
            ad[0] = pk2(a0.x, a0.x); ad[1] = pk2(a0.y, a0.y);
            ad[2] = pk2(a0.z, a0.z); ad[3] = pk2(a0.w, a0.w);
            ad[4] = pk2(a1.x, a1.x); ad[5] = pk2(a1.y, a1.y);
            ad[6] = pk2(a1.z, a1.z); ad[7] = pk2(a1.w, a1.w);
#pragma unroll
            for (int i = 0; i < 8; i++) {
                ffma2(accp[i][0], ad[i], b0);
                ffma2(accp[i][1], ad[i], b1);
                ffma2(accp[i][2], ad[i], b2);
                ffma2(accp[i][3], ad[i], b3);
            }
        }
    }

#pragma unroll
    for (int i = 0; i < 8; i++) {
        const int gmi = m0 + tm * 8 + i;
        const int t = gmi >> 5;
        const int b = gmi & 31;
        float* base = g_xproj + (size_t)t * G4 * BATCH + b;
#pragma unroll
        for (int jp = 0; jp < 4; jp++) {
            float2 v = upk(accp[i][jp]);
            const int n = n0 + tn * 8 + jp * 2;
            base[(size_t)n * BATCH]       = v.x;
            base[(size_t)(n + 1) * BATCH] = v.y;
        }
    }
}

// ---------------------------------------------------------------------------
// Kernel 2: persistent LSTM, 512 threads (16 warps).
// W_hh slice (32 rows x 1024) resident in smem, row stride 1028.
// Warp = (bh 0..1, ks 0..7): batches bh*16..+15, k-slice ks*128..+127.
// Thread tile: 4 rows (rg, rg+8, rg+16, rg+24 == gates 0..3 of n0+rg)
//            x 4 batches (bh*16 + bg, +4, +8, +12), lane = rg*4+bg.
// W via full-width LDS.128 (8 distinct rows/wavefront); h straight from L2
// via __ldcg float4 (each (b,k) consumed by exactly one warp -> no staging).
// k-pair f32x2 accumulators acc[gate][j]; 8-way k partials in smem.
// ---------------------------------------------------------------------------
__global__ void __launch_bounds__(NT, 1) lstm_seq(
    const float* __restrict__ h0,
    const float* __restrict__ c0,
    const float* __restrict__ Whh,
    float* __restrict__ out)
{
    extern __shared__ float sm[];
    float* Ws   = sm;              // 32 * 1028 floats
    float* part = sm + 32 * WSS;   // 8 * 1056 floats

    const int tid = threadIdx.x;
    const int n0  = blockIdx.x * 8;

    // ---- load W_hh slice into smem (once); smem row rr = gate(rr>>3), n(rr&7)
    {
        const int rr = tid >> 4, seg = tid & 15;
        const int grow = (rr >> 3) * HID + n0 + (rr & 7);
        const float4* src = (const float4*)(Whh + (size_t)grow * HID);
        float4* dst = (float4*)(Ws + rr * WSS);
#pragma unroll
        for (int q = 0; q < 16; q++) dst[seg + 16 * q] = src[seg + 16 * q];
    }
    // ---- init h ping-pong buffer 0
    if (tid < 256) {
        const int b = tid >> 3, i = tid & 7;
        g_h[0][b * HID + n0 + i] = h0[b * HID + n0 + i];
    }

    const int wid  = tid >> 5, lane = tid & 31;
    const int ks   = wid & 7;          // k-slice 0..7 (128 k each)
    const int bh   = wid >> 3;         // batch half 0..1
    const int rg   = lane >> 2;        // n-index 0..7 (row set rg+8*gate)
    const int bg   = lane & 3;         // batch group 0..3
    const int b0   = bh * 16 + bg;     // thread batches: b0 + 4*j
    const int fi   = (tid >> 5) & 7, fb = tid & 31;  // finalize role (tid<256)
    const int cidx = fb * HID + n0 + fi;
    float c_reg = (tid < 256) ? c0[cidx] : 0.f;
    float h_reg = 0.f;

    const float* wr = Ws + rg * WSS + ks * 128;   // + gate*8*WSS per row step

    grid_barrier();

    for (int t = 0; t < T_STEPS; t++) {
        const float* hread = g_h[t & 1];
        float* hwrite      = g_h[(t & 1) ^ 1];

        // prefetch x_proj gate contributions (DRAM latency hidden under compute)
        float xg0 = 0.f, xg1 = 0.f, xg2 = 0.f, xg3 = 0.f;
        if (tid < 256) {
            const float* xpt = g_xproj + (size_t)t * G4 * BATCH + fb;
            xg0 = xpt[(size_t)(0 * HID + n0 + fi) * BATCH];
            xg1 = xpt[(size_t)(1 * HID + n0 + fi) * BATCH];
            xg2 = xpt[(size_t)(2 * HID + n0 + fi) * BATCH];
            xg3 = xpt[(size_t)(3 * HID + n0 + fi) * BATCH];
        }

        u64 acc[4][4];
#pragma unroll
        for (int g = 0; g < 4; g++)
#pragma unroll
            for (int j = 0; j < 4; j++) acc[g][j] = 0ull;

        const float* hb = hread + b0 * HID + ks * 128;

#pragma unroll 2
        for (int kq = 0; kq < 32; kq++) {
            float4 hv[4];
#pragma unroll
            for (int j = 0; j < 4; j++)
                hv[j] = __ldcg((const float4*)(hb + j * 4 * HID + kq * 4));
            float4 wv[4];
#pragma unroll
            for (int g = 0; g < 4; g++)
                wv[g] = *(const float4*)(wr + g * 8 * WSS + kq * 4);
#pragma unroll
            for (int g = 0; g < 4; g++) {
                const u64* wp = (const u64*)&wv[g];
#pragma unroll
                for (int j = 0; j < 4; j++) {
                    const u64* hp = (const u64*)&hv[j];
                    ffma2(acc[g][j], wp[0], hp[0]);
                    ffma2(acc[g][j], wp[1], hp[1]);
                }
            }
        }

        // fold k-pairs, write partials: part[ks][r][(b+rg)&31] (rotated cols
        // cut STS bank conflicts; epilogue un-rotates with rg = r&7 = fi)
#pragma unroll
        for (int g = 0; g < 4; g++)
#pragma unroll
            for (int j = 0; j < 4; j++) {
                float2 v = upk(acc[g][j]);
                const int r = rg + 8 * g;
                const int b = b0 + 4 * j;
                part[ks * PKS + r * PRS + ((b + rg) & 31)] = v.x + v.y;
            }
        __syncthreads();

        // gate fusion + state update (thread owns (n0+fi, fb))
        if (tid < 256) {
            const int col = (fb + fi) & 31;
            float g[4] = {xg0, xg1, xg2, xg3};
#pragma unroll
            for (int gg = 0; gg < 4; gg++) {
                const int r = gg * 8 + fi;
#pragma unroll
                for (int kx = 0; kx < 8; kx++)
                    g[gg] += part[kx * PKS + r * PRS + col];
            }
            const float I = 1.f / (1.f + expf(-g[0]));
            const float F = 1.f / (1.f + expf(-g[1]));
            const float G = tanhf(g[2]);
            const float O = 1.f / (1.f + expf(-g[3]));
            c_reg = F * c_reg + I * G;
            h_reg = O * tanhf(c_reg);

            hwrite[cidx] = h_reg;
            out[((size_t)fb * T_STEPS + t) * HID + n0 + fi] = h_reg;
        }

        grid_barrier();
    }

    if (tid < 256) {
        out[OFF_HN + cidx] = h_reg;
        out[OFF_CN + cidx] = c_reg;
    }
}

// ---------------------------------------------------------------------------
extern "C" void kernel_launch(void* const* d_in, const int* in_sizes, int n_in,
                              void* d_out, int out_size)
{
    (void)in_sizes; (void)n_in; (void)out_size;
    const int*   ids = (const int*)  d_in[0];
    const float* h0  = (const float*)d_in[1];
    const float* c0  = (const float*)d_in[2];
    const float* emb = (const float*)d_in[3];
    const float* Wih = (const float*)d_in[4];
    const float* Whh = (const float*)d_in[5];
    float* out = (float*)d_out;

    const int smem_bytes = (32 * WSS + 8 * PKS) * (int)sizeof(float); // 165,376 B
    cudaFuncSetAttribute(lstm_seq, cudaFuncAttributeMaxDynamicSharedMemorySize, smem_bytes);

    dim3 ggrid(G4 / 128, (BATCH * T_STEPS) / 128);
    xproj_gemm<<<ggrid, 256>>>(ids, emb, Wih);
    lstm_seq<<<NB, NT, smem_bytes>>>(h0, c0, Whh, out);
}

// round 8
// speedup vs baseline: 1.6558x; 1.6558x over previous
#include <cuda_runtime.h>
#include <cstdint>
#include <math.h>

#define T_STEPS 512
#define BATCH   32
#define EMBED   512
#define HID     1024
#define G4      4096

#define NB  128
#define NT  512
#define WSS 1028            // W row stride (floats): banks 4*rg distinct, 16B aligned
#define HQ4 33              // h-chunk row stride in float4 (33*16B -> +4 banks/row)
#define PRS 33              // partials row stride (floats)
#define PKS (32 * PRS)      // partials per k-slice

#define OFF_HN ((size_t)BATCH * T_STEPS * HID)
#define OFF_CN (OFF_HN + (size_t)BATCH * HID)

typedef unsigned long long u64;

__device__ float g_xproj[(size_t)T_STEPS * G4 * BATCH]; // [t][j][b]
__device__ float g_h[2][BATCH * HID];
__device__ unsigned g_count;
__device__ volatile unsigned g_gen;

__device__ __forceinline__ void ffma2(u64 &d, u64 a, u64 b) {
    asm("fma.rn.f32x2 %0, %1, %2, %0;" : "+l"(d) : "l"(a), "l"(b));
}
__device__ __forceinline__ u64 pk2(float x, float y) {
    u64 r; asm("mov.b64 %0, {%1, %2};" : "=l"(r) : "f"(x), "f"(y)); return r;
}
__device__ __forceinline__ float2 upk(u64 v) {
    float2 r; asm("mov.b64 {%0, %1}, %2;" : "=f"(r.x), "=f"(r.y) : "l"(v)); return r;
}

__device__ __forceinline__ void grid_barrier() {
    __syncthreads();
    if (threadIdx.x == 0) {
        unsigned gen = g_gen;
        __threadfence();
        unsigned prev = atomicAdd(&g_count, 1u);
        if (prev == NB - 1) {
            g_count = 0;
            __threadfence();
            g_gen = gen + 1;
        } else {
            while (g_gen == gen) { __nanosleep(32); }
        }
        __threadfence();
    }
    __syncthreads();
}

// ---------------------------------------------------------------------------
// Kernel 1: x_proj[t][j][b] = sum_e emb[ids[b][t]][e] * Wih[j][e]  (unchanged)
// ---------------------------------------------------------------------------
__global__ void __launch_bounds__(256, 2) xproj_gemm(
    const int* __restrict__ ids,
    const float* __restrict__ emb,
    const float* __restrict__ Wih)
{
    __shared__ float As[8][132];
    __shared__ float Bs[8][132];

    const int m0  = blockIdx.y * 128;
    const int n0  = blockIdx.x * 128;
    const int tid = threadIdx.x;

    const int mm = tid >> 1;
    const int qa = tid & 1;
    const int gm = m0 + mm;
    const int tt = gm >> 5;
    const int bb = gm & 31;
    const float* arow = emb + (size_t)ids[bb * T_STEPS + tt] * EMBED;
    const float* brow = Wih + (size_t)(n0 + mm) * EMBED;

    const int tm = tid >> 4;
    const int tn = tid & 15;

    u64 accp[8][4];
#pragma unroll
    for (int i = 0; i < 8; i++)
#pragma unroll
        for (int j = 0; j < 4; j++) accp[i][j] = 0ull;

    for (int k0 = 0; k0 < EMBED; k0 += 8) {
        float4 av = *(const float4*)(arow + k0 + qa * 4);
        float4 bv = *(const float4*)(brow + k0 + qa * 4);
        __syncthreads();
        As[qa * 4 + 0][mm] = av.x; As[qa * 4 + 1][mm] = av.y;
        As[qa * 4 + 2][mm] = av.z; As[qa * 4 + 3][mm] = av.w;
        Bs[qa * 4 + 0][mm] = bv.x; Bs[qa * 4 + 1][mm] = bv.y;
        Bs[qa * 4 + 2][mm] = bv.z; Bs[qa * 4 + 3][mm] = bv.w;
        __syncthreads();

#pragma unroll
        for (int kk = 0; kk < 8; kk++) {
            float4 a0 = *(const float4*)(&As[kk][tm * 8]);
            float4 a1 = *(const float4*)(&As[kk][tm * 8 + 4]);
            const u64* bp = (const u64*)(&Bs[kk][tn * 8]);
            u64 b0 = bp[0], b1 = bp[1], b2 = bp[2], b3 = bp[3];
            u64 ad[8];
            ad[0] = pk2(a0.x, a0.x); ad[1] = pk2(a0.y, a0.y);
            ad[2] = pk2(a0.z, a0.z); ad[3] = pk2(a0.w, a0.w);
            ad[4] = pk2(a1.x, a1.x); ad[5] = pk2(a1.y, a1.y);
            ad[6] = pk2(a1.z, a1.z); ad[7] = pk2(a1.w, a1.w);
#pragma unroll
            for (int i = 0; i < 8; i++) {
                ffma2(accp[i][0], ad[i], b0);
                ffma2(accp[i][1], ad[i], b1);
                ffma2(accp[i][2], ad[i], b2);
                ffma2(accp[i][3], ad[i], b3);
            }
        }
    }

#pragma unroll
    for (int i = 0; i < 8; i++) {
        const int gmi = m0 + tm * 8 + i;
        const int t = gmi >> 5;
        const int b = gmi & 31;
        float* base = g_xproj + (size_t)t * G4 * BATCH + b;
#pragma unroll
        for (int jp = 0; jp < 4; jp++) {
            float2 v = upk(accp[i][jp]);
            const int n = n0 + tn * 8 + jp * 2;
            base[(size_t)n * BATCH]       = v.x;
            base[(size_t)(n + 1) * BATCH] = v.y;
        }
    }
}

// ---------------------------------------------------------------------------
// Kernel 2: persistent LSTM, 512 threads (16 warps).
// W_hh slice (32 rows x 1024) resident in smem, stride 1028.
// h staged per 256-k chunk into hq4[kquad][batch] float4 layout (stride 33),
// double-buffered via register prefetch; ONE syncthreads per chunk.
// Warp = (bh 0..1, ks 0..7): 16 batches; k-quads r4 == ks (mod 8) -> every
// warp active in every chunk, 8 quads/chunk, 128 k total.
// Thread = 4 gate-rows (rg + 8g) x 4 batches (bh*16 + bg + 4j), lane=rg*4+bg.
// W: LDS.128 full-width (8 distinct rows). h: LDS.128 4 distinct + broadcast.
// 8-way k-partials overlay h buffer 0; fused gate epilogue on tid<256.
// ---------------------------------------------------------------------------
__global__ void __launch_bounds__(NT, 1) lstm_seq(
    const float* __restrict__ h0,
    const float* __restrict__ c0,
    const float* __restrict__ Whh,
    float* __restrict__ out)
{
    extern __shared__ float sm[];
    float*  Ws   = sm;                        // 32*1028 floats = 131,584 B
    float4* hq4  = (float4*)(sm + 32 * WSS);  // 2 * 64*33 float4 = 67,584 B
    float*  part = (float*)hq4;               // overlay buffer 0 (33,792 B)

    const int tid = threadIdx.x;
    const int n0  = blockIdx.x * 8;

    // ---- load W_hh slice into smem (once); smem row rr = gate(rr>>3), n(rr&7)
    {
        const int rr = tid >> 4, seg = tid & 15;
        const int grow = (rr >> 3) * HID + n0 + (rr & 7);
        const float4* src = (const float4*)(Whh + (size_t)grow * HID);
        float4* dst = (float4*)(Ws + rr * WSS);
#pragma unroll
        for (int q = 0; q < 16; q++) dst[seg + 16 * q] = src[seg + 16 * q];
    }
    // ---- init h ping-pong buffer 0
    if (tid < 256) {
        const int b = tid >> 3, i = tid & 7;
        g_h[0][b * HID + n0 + i] = h0[b * HID + n0 + i];
    }

    const int wid  = tid >> 5, lane = tid & 31;
    const int ks   = wid & 7;          // k-split 0..7
    const int bh   = wid >> 3;         // batch half 0..1
    const int rg   = lane >> 2;        // n-index 0..7
    const int bg   = lane & 3;         // batch group 0..3
    const int b0   = bh * 16 + bg;     // thread batches: b0 + 4*j
    const int sb   = tid >> 4, ss = tid & 15;        // staging role
    const int fi   = (tid >> 5) & 7, fb = tid & 31;  // finalize role (tid<256)
    const int cidx = fb * HID + n0 + fi;
    float c_reg = (tid < 256) ? c0[cidx] : 0.f;
    float h_reg = 0.f;

    // W row pointers for the 4 gates (row = g*8 + rg), k-offset ks*4 floats
    const float* wr0 = Ws + (0 * 8 + rg) * WSS + ks * 4;
    const float* wr1 = Ws + (1 * 8 + rg) * WSS + ks * 4;
    const float* wr2 = Ws + (2 * 8 + rg) * WSS + ks * 4;
    const float* wr3 = Ws + (3 * 8 + rg) * WSS + ks * 4;

    grid_barrier();

    for (int t = 0; t < T_STEPS; t++) {
        const float* hread = g_h[t & 1];
        float* hwrite      = g_h[(t & 1) ^ 1];

        // prefetch x_proj gate contributions (consumed ~6K cycles later)
        float xg0 = 0.f, xg1 = 0.f, xg2 = 0.f, xg3 = 0.f;
        if (tid < 256) {
            const float* xpt = g_xproj + (size_t)t * G4 * BATCH + fb;
            xg0 = xpt[(size_t)(0 * HID + n0 + fi) * BATCH];
            xg1 = xpt[(size_t)(1 * HID + n0 + fi) * BATCH];
            xg2 = xpt[(size_t)(2 * HID + n0 + fi) * BATCH];
            xg3 = xpt[(size_t)(3 * HID + n0 + fi) * BATCH];
        }

        u64 acc[4][4];
#pragma unroll
        for (int g = 0; g < 4; g++)
#pragma unroll
            for (int j = 0; j < 4; j++) acc[g][j] = 0ull;

        // register prefetch of chunk 0 (L2; bypass L1 for cross-SM coherence)
        const float4* gsrc = (const float4*)(hread + sb * HID);
        float4 sreg[4];
#pragma unroll
        for (int i = 0; i < 4; i++) sreg[i] = __ldcg(gsrc + ss + 16 * i);

#pragma unroll 1
        for (int c = 0; c < 4; c++) {
            // stage chunk c: hq4[buf][kql*33 + b]
            float4* buf = hq4 + (c & 1) * (64 * HQ4);
#pragma unroll
            for (int i = 0; i < 4; i++)
                buf[(ss + 16 * i) * HQ4 + sb] = sreg[i];
            // prefetch chunk c+1 into registers
            if (c < 3) {
#pragma unroll
                for (int i = 0; i < 4; i++)
                    sreg[i] = __ldcg(gsrc + (c + 1) * 64 + ss + 16 * i);
            }
            __syncthreads();   // chunk c staged; prior readers of buf are done

            // compute: k-quads r4 = ks + 8m within this chunk
            const float4* hb = buf + ks * HQ4 + b0;
            const float* wc0 = wr0 + c * 256;
            const float* wc1 = wr1 + c * 256;
            const float* wc2 = wr2 + c * 256;
            const float* wc3 = wr3 + c * 256;
#pragma unroll
            for (int m = 0; m < 8; m++) {
                float4 hv[4];
#pragma unroll
                for (int j = 0; j < 4; j++)
                    hv[j] = hb[m * 8 * HQ4 + 4 * j];
                float4 wv[4];
                wv[0] = *(const float4*)(wc0 + m * 32);
                wv[1] = *(const float4*)(wc1 + m * 32);
                wv[2] = *(const float4*)(wc2 + m * 32);
                wv[3] = *(const float4*)(wc3 + m * 32);
#pragma unroll
                for (int g = 0; g < 4; g++) {
                    const u64* wp = (const u64*)&wv[g];
#pragma unroll
                    for (int j = 0; j < 4; j++) {
                        const u64* hp = (const u64*)&hv[j];
                        ffma2(acc[g][j], wp[0], hp[0]);
                        ffma2(acc[g][j], wp[1], hp[1]);
                    }
                }
            }
        }

        // fold k-pairs, write partials: part[ks][r][(b+r)&31] (rotated cols,
        // <=2-way STS conflicts; epilogue un-rotates). Overlay on buffer 0 is
        // safe: all warps passed sync(c=3) -> no buffer-0 readers remain.
#pragma unroll
        for (int g = 0; g < 4; g++)
#pragma unroll
            for (int j = 0; j < 4; j++) {
                float2 v = upk(acc[g][j]);
                const int r = rg + 8 * g;
                const int b = b0 + 4 * j;
                part[ks * PKS + r * PRS + ((b + r) & 31)] = v.x + v.y;
            }
        __syncthreads();

        // gate fusion + state update (thread owns (n0+fi, fb))
        if (tid < 256) {
            float g[4] = {xg0, xg1, xg2, xg3};
#pragma unroll
            for (int gg = 0; gg < 4; gg++) {
                const int r = gg * 8 + fi;
                const int col = (fb + r) & 31;
#pragma unroll
                for (int kx = 0; kx < 8; kx++)
                    g[gg] += part[kx * PKS + r * PRS + col];
            }
            const float I = 1.f / (1.f + expf(-g[0]));
            const float F = 1.f / (1.f + expf(-g[1]));
            const float G = tanhf(g[2]);
            const float O = 1.f / (1.f + expf(-g[3]));
            c_reg = F * c_reg + I * G;
            h_reg = O * tanhf(c_reg);

            hwrite[cidx] = h_reg;
            out[((size_t)fb * T_STEPS + t) * HID + n0 + fi] = h_reg;
        }

        grid_barrier();
    }

    if (tid < 256) {
        out[OFF_HN + cidx] = h_reg;
        out[OFF_CN + cidx] = c_reg;
    }
}

// ---------------------------------------------------------------------------
extern "C" void kernel_launch(void* const* d_in, const int* in_sizes, int n_in,
                              void* d_out, int out_size)
{
    (void)in_sizes; (void)n_in; (void)out_size;
    const int*   ids = (const int*)  d_in[0];
    const float* h0  = (const float*)d_in[1];
    const float* c0  = (const float*)d_in[2];
    const float* emb = (const float*)d_in[3];
    const float* Wih = (const float*)d_in[4];
    const float* Whh = (const float*)d_in[5];
    float* out = (float*)d_out;

    const int smem_bytes = 32 * WSS * 4 + 2 * 64 * HQ4 * 16; // 199,168 B
    cudaFuncSetAttribute(lstm_seq, cudaFuncAttributeMaxDynamicSharedMemorySize, smem_bytes);

    dim3 ggrid(G4 / 128, (BATCH * T_STEPS) / 128);
    xproj_gemm<<<ggrid, 256>>>(ids, emb, Wih);
    lstm_seq<<<NB, NT, smem_bytes>>>(h0, c0, Whh, out);
}